// round 16
// baseline (speedup 1.0000x reference)
#include <cuda_runtime.h>
#include <math.h>
#include <stdint.h>

// ---------------- Problem constants ----------------
#define NROWS 1024
#define NCLS  100000
#define DIM   512
#define NB4   592            // CTAs with 128-col tiles -> cols [0, 75776)
#define NB3   296            // CTAs with 96-col tiles  -> cols [75776, 104192)
#define SCALE 64.0f
#define MARG  0.5f
#define COS_M 0.87758256189037271611f
#define SIN_M 0.47942553860420300027f
#define MIN_COS (-0.87758256189037271611f)
#define FP8_SCALE 16.0f      // power of 2: exact; acc = 256 * cos

// Packed-B capacity: 104192 cols -> 13024 col8 groups (zero-filled tail, .bss)
#define WB_USHORTS ((size_t)13024 * 2048)

// ---------------- Scratch (device globals) ----------------
__device__ float g_fn[NROWS * DIM];                 // normalized feats fp32 (label path)
__device__ unsigned short g_fnb8[NROWS * DIM / 2];  // feats e4m3 packed (LDS.128 frags)
__device__ unsigned short g_wnb8[WB_USHORTS];       // W normalized e4m3 packed (LDS.64 frags)
__device__ float g_winv[NCLS];
__device__ float g_sum[NROWS];                      // atomically accumulated sumexp
__device__ float g_cosl[NROWS];                     // fp8-replica label LOGIT (cancellation)
__device__ float g_tgt[NROWS];                      // exact margin target

// ---------------- helpers ----------------
__device__ __forceinline__ uint32_t smem_u32(const void* p) {
    uint32_t a;
    asm("{ .reg .u64 t; cvta.to.shared.u64 t, %1; cvt.u32.u64 %0, t; }" : "=r"(a) : "l"(p));
    return a;
}
__device__ __forceinline__ void cp16(uint32_t dst, const void* src) {
    asm volatile("cp.async.cg.shared.global [%0], [%1], 16;" :: "r"(dst), "l"(src) : "memory");
}
template <int N>
__device__ __forceinline__ void cp_wait() {
    asm volatile("cp.async.wait_group %0;" :: "n"(N) : "memory");
}
__device__ __forceinline__ unsigned short cvt_e4m3x2(float hi, float lo) {
    unsigned short r;
    asm("cvt.rn.satfinite.e4m3x2.f32 %0, %1, %2;" : "=h"(r) : "f"(hi), "f"(lo));
    return r;
}
// e4m3x2 -> two floats, pure PTX (no cuda_fp16.h dependency)
__device__ __forceinline__ void e4m3x2_to_ff(unsigned short u, float& lo, float& hi) {
    uint32_t h2;
    asm("cvt.rn.f16x2.e4m3x2 %0, %1;" : "=r"(h2) : "h"(u));
    unsigned short hlo = (unsigned short)(h2 & 0xFFFFu);
    unsigned short hhi = (unsigned short)(h2 >> 16);
    asm("{ .reg .b16 t; mov.b16 t, %1; cvt.f32.f16 %0, t; }" : "=f"(lo) : "h"(hlo));
    asm("{ .reg .b16 t; mov.b16 t, %1; cvt.f32.f16 %0, t; }" : "=f"(hi) : "h"(hhi));
}
__device__ __forceinline__ void mma_fp8(float* d, const uint32_t* a, const uint32_t* b) {
    asm volatile(
        "mma.sync.aligned.m16n8k32.row.col.f32.e4m3.e4m3.f32 "
        "{%0,%1,%2,%3}, {%4,%5,%6,%7}, {%8,%9}, {%0,%1,%2,%3};"
        : "+f"(d[0]), "+f"(d[1]), "+f"(d[2]), "+f"(d[3])
        : "r"(a[0]), "r"(a[1]), "r"(a[2]), "r"(a[3]), "r"(b[0]), "r"(b[1]));
}

// A-pack: byte offset for element (row, k). 16B unit = one thread's 4-reg fragment
// of a (16row x 32k) block -> LDS.128 per fragment.
__device__ __forceinline__ uint32_t a_pack_byte(int row, int k) {
    int row16 = row >> 4, rl = row & 15, half = rl >> 3, l4 = rl & 7;
    int kblk = k >> 5, kk = k & 31, q = kk >> 4, lm = (kk >> 2) & 3, b = kk & 3;
    int lane = l4 * 4 + lm;
    return ((uint32_t)((row16 * 16 + kblk) * 32 + lane)) * 16 + q * 8 + half * 4 + b;
}
// B-pack: byte offset for element (col, k). 8B unit per lane per (8col x 32k) block.
__device__ __forceinline__ uint32_t b_pack_byte(int col, int k) {
    int col8 = col >> 3, l4 = col & 7;
    int kblk = k >> 5, kk = k & 31, q = kk >> 4, lm = (kk >> 2) & 3, b = kk & 3;
    int lane = l4 * 4 + lm;
    return ((uint32_t)((col8 * 16 + kblk) * 32 + lane)) * 8 + q * 4 + b;
}

// ---------------------------------------------------------------------------
// Kernel 1: normalize feats rows -> fp32 + packed e4m3(x16); zero g_sum.
__global__ void k_norm_feats(const float* __restrict__ feats) {
    int row = blockIdx.x;
    int t = threadIdx.x;
    if (t == 0) g_sum[row] = 0.f;            // deterministic re-init each replay
    const float2* x = (const float2*)(feats + row * DIM);
    float2 v[2];
    v[0] = x[t]; v[1] = x[t + 128];
    float ss = v[0].x * v[0].x + v[0].y * v[0].y + v[1].x * v[1].x + v[1].y * v[1].y;
#pragma unroll
    for (int off = 16; off > 0; off >>= 1) ss += __shfl_xor_sync(0xffffffffu, ss, off);
    __shared__ float sred[4];
    __shared__ float srinv;
    int lane = t & 31, wp = t >> 5;
    if (lane == 0) sred[wp] = ss;
    __syncthreads();
    if (t == 0) {
        float tot = sred[0] + sred[1] + sred[2] + sred[3];
        srinv = 1.f / fmaxf(sqrtf(tot), 1e-12f);
    }
    __syncthreads();
    float rinv = srinv;
#pragma unroll
    for (int i = 0; i < 2; i++) {
        int j = t + i * 128;
        float yx = v[i].x * rinv, yy = v[i].y * rinv;
        g_fn[row * DIM + 2 * j] = yx;
        g_fn[row * DIM + 2 * j + 1] = yy;
        uint32_t ba = a_pack_byte(row, 2 * j);
        g_fnb8[ba >> 1] = cvt_e4m3x2(yy * FP8_SCALE, yx * FP8_SCALE);
    }
}

// ---------------------------------------------------------------------------
// Kernel 2: normalize W rows -> packed e4m3(x16) + winv. One warp per row.
// float4 loads + 4-byte packed fp8 stores.
__global__ void k_wnorm(const float* __restrict__ w) {
    int wp = threadIdx.x >> 5, lane = threadIdx.x & 31;
    int row = blockIdx.x * 8 + wp;
    if (row >= NCLS) return;
    const float4* x = (const float4*)(w + (size_t)row * DIM);
    float4 v[4];
    float ss = 0.f;
#pragma unroll
    for (int i = 0; i < 4; i++) {
        v[i] = x[lane + i * 32];
        ss += v[i].x * v[i].x + v[i].y * v[i].y + v[i].z * v[i].z + v[i].w * v[i].w;
    }
#pragma unroll
    for (int off = 16; off > 0; off >>= 1) ss += __shfl_xor_sync(0xffffffffu, ss, off);
    float rinv = 1.f / fmaxf(sqrtf(ss), 1e-12f);
    float rs16 = rinv * FP8_SCALE;
#pragma unroll
    for (int i = 0; i < 4; i++) {
        int k0 = 4 * (lane + i * 32);
        unsigned short u0 = cvt_e4m3x2(v[i].y * rs16, v[i].x * rs16);
        unsigned short u1 = cvt_e4m3x2(v[i].w * rs16, v[i].z * rs16);
        uint32_t packed = (uint32_t)u0 | ((uint32_t)u1 << 16);
        *(uint32_t*)((char*)g_wnb8 + b_pack_byte(row, k0)) = packed;
    }
    if (lane == 0) g_winv[row] = rinv;
}

// ---------------------------------------------------------------------------
// GEMM body: K=128 chunks, TRIPLE-buffered A, ONE barrier per iteration,
// prefetch depth 2, immediate-offset fragment addressing.
// SMEM layout: [0, 49152) three 16 KB A buffers (s_red overlaid in the
// just-consumed buffer during epilogues); [49152, +TN*16384) B resident.
#define OFF_B   49152
#define SMEM_BYTES (OFF_B + 4 * 16384)   // TN=4 -> 114688; 2 CTAs/SM (229 KB)

template <int TN>
__device__ __forceinline__ void gemm_body(int colBase) {
    extern __shared__ char sm[];
    const uint32_t sb = smem_u32(sm);
    const uint32_t aBuf[3] = { sb, sb + 16384, sb + 32768 };

    const int tid = threadIdx.x;
    const int wid = tid >> 5, lane = tid & 31;
    const int l4 = lane >> 2, lm = lane & 3;
    const int warpM = (wid & 1) * 64;
    const int warpN = (wid >> 1) * (TN * 8);
    const int mbBase = (wid & 1) * 4;
    const int nbBase = (wid >> 1) * TN;

    // Per-warp fragment base pointers (loop-invariant).
    const char* aFragBase[3] = {
        sm + mbBase * 2048 + lane * 16,
        sm + 16384 + mbBase * 2048 + lane * 16,
        sm + 32768 + mbBase * 2048 + lane * 16
    };
    const char* bFragBase0 = sm + OFF_B + nbBase * 4096 + lane * 8;

    // ---- B resident: contiguous packed stripe, TN*16 KB ----
    {
        const char* wsrc = (const char*)g_wnb8 + (size_t)(colBase >> 3) * 4096;
        uint32_t dst = sb + OFF_B + (uint32_t)tid * 16;
        const char* src = wsrc + (size_t)tid * 16;
#pragma unroll
        for (int i = 0; i < TN * 4; i++)
            cp16(dst + i * 4096, src + (size_t)i * 4096);
        asm volatile("cp.async.commit_group;" ::: "memory");
    }

    // ---- A chunk loader: it = mt*4 + kc covers rows mt*128.., K kc*128.. ----
    const char* aSrcTid = (const char*)g_fnb8 + (size_t)(tid >> 7) * 8192 + (tid & 127) * 16;
    auto loadA = [&](int it) {
        const char* src = aSrcTid + (size_t)(it >> 2) * 65536 + (it & 3) * 2048;
        uint32_t dst = aBuf[it % 3] + (uint32_t)tid * 16;
#pragma unroll
        for (int i = 0; i < 4; i++)
            cp16(dst + i * 4096, src + i * 16384);
        asm volatile("cp.async.commit_group;" ::: "memory");
    };
    loadA(0);
    loadA(1);

    float acc[4][TN][4];
#pragma unroll
    for (int i = 0; i < 4; i++)
#pragma unroll
        for (int j = 0; j < TN; j++)
#pragma unroll
            for (int e = 0; e < 4; e++) acc[i][j][e] = 0.f;

#pragma unroll 1
    for (int it = 0; it < 32; it++) {
        const int kc = it & 3;
        if (it < 31) cp_wait<1>(); else cp_wait<0>();   // loadA(it) complete
        __syncthreads();                                 // single barrier
        if (it + 2 < 32) loadA(it + 2);                  // after barrier: no laggard overlap

        const char* Ab = aFragBase[it % 3];          // + tm*2048 + ks*512
        const char* Bb = bFragBase0 + kc * 1024;     // + tn*4096 + ks*256

        // ---- 2-stage fragment pipeline over ks (immediate offsets only) ----
        uint32_t af[2][4][4], bf[2][TN][2];
#pragma unroll
        for (int tm = 0; tm < 4; tm++) {
            uint4 t4 = *(const uint4*)(Ab + tm * 2048);
            af[0][tm][0] = t4.x; af[0][tm][1] = t4.y; af[0][tm][2] = t4.z; af[0][tm][3] = t4.w;
        }
#pragma unroll
        for (int tn = 0; tn < TN; tn++) {
            uint2 t2 = *(const uint2*)(Bb + tn * 4096);
            bf[0][tn][0] = t2.x; bf[0][tn][1] = t2.y;
        }
#pragma unroll
        for (int ks = 0; ks < 4; ks++) {
            const int cur = ks & 1, nxt = cur ^ 1;
            if (ks < 3) {
#pragma unroll
                for (int tm = 0; tm < 4; tm++) {
                    uint4 t4 = *(const uint4*)(Ab + tm * 2048 + (ks + 1) * 512);
                    af[nxt][tm][0] = t4.x; af[nxt][tm][1] = t4.y;
                    af[nxt][tm][2] = t4.z; af[nxt][tm][3] = t4.w;
                }
#pragma unroll
                for (int tn = 0; tn < TN; tn++) {
                    uint2 t2 = *(const uint2*)(Bb + tn * 4096 + (ks + 1) * 256);
                    bf[nxt][tn][0] = t2.x; bf[nxt][tn][1] = t2.y;
                }
            }
#pragma unroll
            for (int tm = 0; tm < 4; tm++)
#pragma unroll
                for (int tn = 0; tn < TN; tn++)
                    mma_fp8(acc[tm][tn], af[cur][tm], bf[cur][tn]);
        }

        // ---- per-M-tile epilogue; s_red overlaid in just-consumed A buffer ----
        if (kc == 3) {
            __syncthreads();   // all mma reads of buffer it%3 complete
            float* s_red = (float*)(sm + (it % 3) * 16384);
            const int rowBase = (it >> 2) * 128;
            float rs[4][2];
#pragma unroll
            for (int tm = 0; tm < 4; tm++) { rs[tm][0] = 0.f; rs[tm][1] = 0.f; }
#pragma unroll
            for (int tn = 0; tn < TN; tn++) {
                int lc = warpN + tn * 8 + 2 * lm;
                int gc0 = colBase + lc, gc1 = gc0 + 1;
                float m0 = (gc0 < NCLS) ? 1.f : 0.f;
                float m1 = (gc1 < NCLS) ? 1.f : 0.f;
#pragma unroll
                for (int tm = 0; tm < 4; tm++) {
                    // logit = 64*cos = acc * 0.25 (acc = 256*cos); clamp [-64,64]
                    float c0 = fminf(fmaxf(acc[tm][tn][0] * 0.25f, -64.f), 64.f);
                    float c1 = fminf(fmaxf(acc[tm][tn][1] * 0.25f, -64.f), 64.f);
                    float c2 = fminf(fmaxf(acc[tm][tn][2] * 0.25f, -64.f), 64.f);
                    float c3 = fminf(fmaxf(acc[tm][tn][3] * 0.25f, -64.f), 64.f);
                    rs[tm][0] += m0 * __expf(c0 - 64.f) + m1 * __expf(c1 - 64.f);
                    rs[tm][1] += m0 * __expf(c2 - 64.f) + m1 * __expf(c3 - 64.f);
                    acc[tm][tn][0] = 0.f; acc[tm][tn][1] = 0.f;
                    acc[tm][tn][2] = 0.f; acc[tm][tn][3] = 0.f;
                }
            }
#pragma unroll
            for (int tm = 0; tm < 4; tm++)
#pragma unroll
                for (int h = 0; h < 2; h++) {
                    float v = rs[tm][h];
                    v += __shfl_xor_sync(0xffffffffu, v, 1);
                    v += __shfl_xor_sync(0xffffffffu, v, 2);
                    rs[tm][h] = v;
                }
            if (lm == 0) {
                int wn = wid >> 1;
#pragma unroll
                for (int tm = 0; tm < 4; tm++) {
                    int r0 = warpM + tm * 16 + l4;
                    s_red[wn * 128 + r0] = rs[tm][0];
                    s_red[wn * 128 + r0 + 8] = rs[tm][1];
                }
            }
            __syncthreads();
            if (tid < 128) {
                float s = s_red[tid] + s_red[128 + tid] + s_red[256 + tid] + s_red[384 + tid];
                atomicAdd(&g_sum[rowBase + tid], s);
            }
            // next write to buffer it%3 is loadA(it+3), issued only after the
            // top barrier of iteration it+1 -> all s_red reads are done by then.
        }
    }
}

// Kernel 3: merged GEMM launch. First NB4 blocks: 128-col tiles; rest: 96-col.
__global__ void __launch_bounds__(256, 2)
k_main_fp8() {
    if (blockIdx.x < NB4) {
        gemm_body<4>(blockIdx.x * 128);
    } else {
        gemm_body<3>(NB4 * 128 + (blockIdx.x - NB4) * 96);
    }
}

// ---------------------------------------------------------------------------
// Kernel 4: exact fp32 label cos -> margin target, PLUS fp8-replica label
// logit (same packed operands as the GEMM) for near-exact cancellation.
__global__ void k_label(const float* __restrict__ w, const int* __restrict__ labels) {
    int wp = threadIdx.x >> 5, lane = threadIdx.x & 31;
    int n = blockIdx.x * 8 + wp;
    if (n >= NROWS) return;
    int lab = labels[n];
    const float* fr = g_fn + n * DIM;
    const float* wr = w + (size_t)lab * DIM;
    float dot = 0.f;
    float d8 = 0.f;
#pragma unroll
    for (int i = 0; i < 16; i++) dot += fr[lane + i * 32] * wr[lane + i * 32];
    // fp8-replica dot: lane handles k in [lane*16, lane*16+16)
#pragma unroll
    for (int j = 0; j < 8; j++) {
        int k0 = lane * 16 + 2 * j;
        float ax, ay, bx, by;
        e4m3x2_to_ff(g_fnb8[a_pack_byte(n, k0) >> 1], ax, ay);
        e4m3x2_to_ff(g_wnb8[b_pack_byte(lab, k0) >> 1], bx, by);
        d8 += ax * bx + ay * by;
    }
#pragma unroll
    for (int off = 16; off > 0; off >>= 1) {
        dot += __shfl_xor_sync(0xffffffffu, dot, off);
        d8 += __shfl_xor_sync(0xffffffffu, d8, off);
    }
    if (lane == 0) {
        float cosv = fminf(fmaxf(dot * g_winv[lab], -1.f), 1.f);
        float sinv = sqrtf(1.f - cosv * cosv + 1e-5f);
        float cm = cosv * COS_M - sinv * SIN_M;
        g_tgt[n] = (cosv > MIN_COS) ? cm : (cosv - sinv * MARG);
        g_cosl[n] = fminf(fmaxf(d8 * 0.25f, -64.f), 64.f);   // replica label logit
    }
}

// ---------------------------------------------------------------------------
// Kernel 5: label swap, NLL, mean. g_sum already accumulated.
__global__ void k_final(float* __restrict__ out) {
    int t = threadIdx.x;
    float s = g_sum[t];
    float cl = g_cosl[t];                        // (replica of) label logit inside s
    float tgt = g_tgt[t];
    float s2 = s - expf(cl - 64.f) + expf(SCALE * tgt - 64.f);
    float nll = 64.f + logf(s2) - SCALE * tgt;

    __shared__ float sred[1024];
    sred[t] = nll;
    __syncthreads();
    for (int off = 512; off > 0; off >>= 1) {
        if (t < off) sred[t] += sred[t + off];
        __syncthreads();
    }
    if (t == 0) out[0] = sred[0] * (1.0f / (float)NROWS);
}

// ---------------------------------------------------------------------------
extern "C" void kernel_launch(void* const* d_in, const int* in_sizes, int n_in,
                              void* d_out, int out_size) {
    const float* feats = (const float*)d_in[0];
    const float* w = (const float*)d_in[1];
    const int* labels = (const int*)d_in[2];
    float* out = (float*)d_out;

    cudaFuncSetAttribute(k_main_fp8, cudaFuncAttributeMaxDynamicSharedMemorySize, SMEM_BYTES);

    k_norm_feats<<<NROWS, 128>>>(feats);
    k_wnorm<<<(NCLS + 7) / 8, 256>>>(w);
    k_main_fp8<<<NB4 + NB3, 256, SMEM_BYTES>>>();
    k_label<<<NROWS / 8, 256>>>(w, labels);
    k_final<<<1, 1024>>>(out);
}

// round 17
// speedup vs baseline: 1.0358x; 1.0358x over previous
#include <cuda_runtime.h>
#include <math.h>
#include <stdint.h>

// ---------------- Problem constants ----------------
#define NROWS 1024
#define NCLS  100000
#define DIM   512
#define NB4   592            // CTAs with 128-col tiles -> cols [0, 75776)
#define NB3   296            // CTAs with 96-col tiles  -> cols [75776, 104192)
#define SCALE 64.0f
#define MARG  0.5f
#define COS_M 0.87758256189037271611f
#define SIN_M 0.47942553860420300027f
#define MIN_COS (-0.87758256189037271611f)
#define FP8_SCALE 16.0f      // power of 2: exact; acc = 256 * cos

// ---------------- Scratch (device globals) ----------------
__device__ float g_fn[NROWS * DIM];                 // normalized feats fp32 (label path)
__device__ unsigned short g_fnb8[NROWS * DIM / 2];  // feats e4m3 packed (LDS.128 frags)
__device__ float g_sum[NROWS];                      // atomically accumulated sumexp
__device__ float g_cosl[NROWS];                     // fp8-replica label LOGIT (cancellation)
__device__ float g_tgt[NROWS];                      // exact margin target

// ---------------- helpers ----------------
__device__ __forceinline__ uint32_t smem_u32(const void* p) {
    uint32_t a;
    asm("{ .reg .u64 t; cvta.to.shared.u64 t, %1; cvt.u32.u64 %0, t; }" : "=r"(a) : "l"(p));
    return a;
}
__device__ __forceinline__ void cp16(uint32_t dst, const void* src) {
    asm volatile("cp.async.cg.shared.global [%0], [%1], 16;" :: "r"(dst), "l"(src) : "memory");
}
template <int N>
__device__ __forceinline__ void cp_wait() {
    asm volatile("cp.async.wait_group %0;" :: "n"(N) : "memory");
}
__device__ __forceinline__ unsigned short cvt_e4m3x2(float hi, float lo) {
    unsigned short r;
    asm("cvt.rn.satfinite.e4m3x2.f32 %0, %1, %2;" : "=h"(r) : "f"(hi), "f"(lo));
    return r;
}
// e4m3x2 -> two floats, pure PTX (no cuda_fp16.h dependency)
__device__ __forceinline__ void e4m3x2_to_ff(unsigned short u, float& lo, float& hi) {
    uint32_t h2;
    asm("cvt.rn.f16x2.e4m3x2 %0, %1;" : "=r"(h2) : "h"(u));
    unsigned short hlo = (unsigned short)(h2 & 0xFFFFu);
    unsigned short hhi = (unsigned short)(h2 >> 16);
    asm("{ .reg .b16 t; mov.b16 t, %1; cvt.f32.f16 %0, t; }" : "=f"(lo) : "h"(hlo));
    asm("{ .reg .b16 t; mov.b16 t, %1; cvt.f32.f16 %0, t; }" : "=f"(hi) : "h"(hhi));
}
__device__ __forceinline__ void mma_fp8(float* d, const uint32_t* a, const uint32_t* b) {
    asm volatile(
        "mma.sync.aligned.m16n8k32.row.col.f32.e4m3.e4m3.f32 "
        "{%0,%1,%2,%3}, {%4,%5,%6,%7}, {%8,%9}, {%0,%1,%2,%3};"
        : "+f"(d[0]), "+f"(d[1]), "+f"(d[2]), "+f"(d[3])
        : "r"(a[0]), "r"(a[1]), "r"(a[2]), "r"(a[3]), "r"(b[0]), "r"(b[1]));
}

// A-pack: byte offset for element (row, k). 16B unit = one thread's 4-reg fragment
// of a (16row x 32k) block -> LDS.128 per fragment.
__device__ __forceinline__ uint32_t a_pack_byte(int row, int k) {
    int row16 = row >> 4, rl = row & 15, half = rl >> 3, l4 = rl & 7;
    int kblk = k >> 5, kk = k & 31, q = kk >> 4, lm = (kk >> 2) & 3, b = kk & 3;
    int lane = l4 * 4 + lm;
    return ((uint32_t)((row16 * 16 + kblk) * 32 + lane)) * 16 + q * 8 + half * 4 + b;
}
// B-pack: byte offset for element (col, k). 8B unit per lane per (8col x 32k) block.
__device__ __forceinline__ uint32_t b_pack_byte(int col, int k) {
    int col8 = col >> 3, l4 = col & 7;
    int kblk = k >> 5, kk = k & 31, q = kk >> 4, lm = (kk >> 2) & 3, b = kk & 3;
    int lane = l4 * 4 + lm;
    return ((uint32_t)((col8 * 16 + kblk) * 32 + lane)) * 8 + q * 4 + b;
}

// ---------------------------------------------------------------------------
// Kernel 1: normalize feats rows -> fp32 + packed e4m3(x16); zero g_sum.
__global__ void k_norm_feats(const float* __restrict__ feats) {
    int row = blockIdx.x;
    int t = threadIdx.x;
    if (t == 0) g_sum[row] = 0.f;            // deterministic re-init each replay
    const float2* x = (const float2*)(feats + row * DIM);
    float2 v[2];
    v[0] = x[t]; v[1] = x[t + 128];
    float ss = v[0].x * v[0].x + v[0].y * v[0].y + v[1].x * v[1].x + v[1].y * v[1].y;
#pragma unroll
    for (int off = 16; off > 0; off >>= 1) ss += __shfl_xor_sync(0xffffffffu, ss, off);
    __shared__ float sred[4];
    __shared__ float srinv;
    int lane = t & 31, wp = t >> 5;
    if (lane == 0) sred[wp] = ss;
    __syncthreads();
    if (t == 0) {
        float tot = sred[0] + sred[1] + sred[2] + sred[3];
        srinv = 1.f / fmaxf(sqrtf(tot), 1e-12f);
    }
    __syncthreads();
    float rinv = srinv;
#pragma unroll
    for (int i = 0; i < 2; i++) {
        int j = t + i * 128;
        float yx = v[i].x * rinv, yy = v[i].y * rinv;
        g_fn[row * DIM + 2 * j] = yx;
        g_fn[row * DIM + 2 * j + 1] = yy;
        uint32_t ba = a_pack_byte(row, 2 * j);
        g_fnb8[ba >> 1] = cvt_e4m3x2(yy * FP8_SCALE, yx * FP8_SCALE);
    }
}

// ---------------------------------------------------------------------------
// GEMM body: K=128 chunks, double buffer, 2 syncs, 2-stage fragment pipeline,
// immediate-offset addressing. W normalization + fp8 quantization FUSED into
// the prologue: each CTA converts its own B stripe fp32 -> packed e4m3 in smem.
#define OFF_RED 0        // 512 floats
#define OFF_A0  2048     // 16 KB
#define OFF_A1  18432    // 16 KB
#define OFF_B   34816    // TN*16 KB resident
#define SMEM_BYTES (OFF_B + 4 * 16384)   // sized for TN=4 -> 100352; 2 CTAs/SM

template <int TN>
__device__ __forceinline__ void gemm_body(const float* __restrict__ w, int colBase) {
    extern __shared__ char sm[];
    float* s_red = (float*)sm;
    const uint32_t sb = smem_u32(sm);
    const uint32_t aBuf[2] = { sb + OFF_A0, sb + OFF_A1 };

    const int tid = threadIdx.x;
    const int wid = tid >> 5, lane = tid & 31;
    const int l4 = lane >> 2, lm = lane & 3;
    const int warpM = (wid & 1) * 64;
    const int warpN = (wid >> 1) * (TN * 8);
    const int mbBase = (wid & 1) * 4;
    const int nbBase = (wid >> 1) * TN;

    // Per-warp fragment base pointers (loop-invariant).
    const char* aFragBase[2] = {
        sm + OFF_A0 + mbBase * 2048 + lane * 16,
        sm + OFF_A1 + mbBase * 2048 + lane * 16
    };
    const char* bFragBase0 = sm + OFF_B + nbBase * 4096 + lane * 8;

    // ---- A chunk loader (issue first: overlaps the B-convert prologue) ----
    const char* aSrcTid = (const char*)g_fnb8 + (size_t)(tid >> 7) * 8192 + (tid & 127) * 16;
    auto loadA = [&](int it, int buf) {
        const char* src = aSrcTid + (size_t)(it >> 2) * 65536 + (it & 3) * 2048;
        uint32_t dst = aBuf[buf] + (uint32_t)tid * 16;
#pragma unroll
        for (int i = 0; i < 4; i++)
            cp16(dst + i * 4096, src + i * 16384);
        asm volatile("cp.async.commit_group;" ::: "memory");
    };
    loadA(0, 0);

    // ---- Fused B prologue: normalize + quantize this CTA's W stripe ----
    // Each warp handles TN*4 consecutive local cols; one col per pass.
    {
        const int cpw = TN * 4;
#pragma unroll 1
        for (int c = 0; c < cpw; c++) {
            int lc = wid * cpw + c;
            int gcol = colBase + lc;
            float4 v[4];
            float ss = 0.f;
            if (gcol < NCLS) {
                const float4* src = (const float4*)(w + (size_t)gcol * DIM);
#pragma unroll
                for (int i = 0; i < 4; i++) {
                    v[i] = src[lane + i * 32];
                    ss += v[i].x * v[i].x + v[i].y * v[i].y + v[i].z * v[i].z + v[i].w * v[i].w;
                }
            } else {
#pragma unroll
                for (int i = 0; i < 4; i++) v[i] = make_float4(0.f, 0.f, 0.f, 0.f);
            }
#pragma unroll
            for (int off = 16; off > 0; off >>= 1) ss += __shfl_xor_sync(0xffffffffu, ss, off);
            float rs16 = (gcol < NCLS) ? (FP8_SCALE / fmaxf(sqrtf(ss), 1e-12f)) : 0.f;
#pragma unroll
            for (int i = 0; i < 4; i++) {
                int k0 = 4 * (lane + i * 32);
                unsigned short u0 = cvt_e4m3x2(v[i].y * rs16, v[i].x * rs16);
                unsigned short u1 = cvt_e4m3x2(v[i].w * rs16, v[i].z * rs16);
                uint32_t packed = (uint32_t)u0 | ((uint32_t)u1 << 16);
                *(uint32_t*)(sm + OFF_B + b_pack_byte(lc, k0)) = packed;
            }
        }
    }

    float acc[4][TN][4];
#pragma unroll
    for (int i = 0; i < 4; i++)
#pragma unroll
        for (int j = 0; j < TN; j++)
#pragma unroll
            for (int e = 0; e < 4; e++) acc[i][j][e] = 0.f;

#pragma unroll 1
    for (int it = 0; it < 32; it++) {
        const int kc = it & 3;
        if (it + 1 < 32) {
            loadA(it + 1, (it + 1) & 1);
            cp_wait<1>();
        } else {
            cp_wait<0>();
        }
        __syncthreads();   // also publishes the B prologue STS on it==0

        const char* Ab = aFragBase[it & 1];          // + tm*2048 + ks*512
        const char* Bb = bFragBase0 + kc * 1024;     // + tn*4096 + ks*256

        // ---- 2-stage fragment pipeline over ks (immediate offsets only) ----
        uint32_t af[2][4][4], bf[2][TN][2];
#pragma unroll
        for (int tm = 0; tm < 4; tm++) {
            uint4 t4 = *(const uint4*)(Ab + tm * 2048);
            af[0][tm][0] = t4.x; af[0][tm][1] = t4.y; af[0][tm][2] = t4.z; af[0][tm][3] = t4.w;
        }
#pragma unroll
        for (int tn = 0; tn < TN; tn++) {
            uint2 t2 = *(const uint2*)(Bb + tn * 4096);
            bf[0][tn][0] = t2.x; bf[0][tn][1] = t2.y;
        }
#pragma unroll
        for (int ks = 0; ks < 4; ks++) {
            const int cur = ks & 1, nxt = cur ^ 1;
            if (ks < 3) {
#pragma unroll
                for (int tm = 0; tm < 4; tm++) {
                    uint4 t4 = *(const uint4*)(Ab + tm * 2048 + (ks + 1) * 512);
                    af[nxt][tm][0] = t4.x; af[nxt][tm][1] = t4.y;
                    af[nxt][tm][2] = t4.z; af[nxt][tm][3] = t4.w;
                }
#pragma unroll
                for (int tn = 0; tn < TN; tn++) {
                    uint2 t2 = *(const uint2*)(Bb + tn * 4096 + (ks + 1) * 256);
                    bf[nxt][tn][0] = t2.x; bf[nxt][tn][1] = t2.y;
                }
            }
#pragma unroll
            for (int tm = 0; tm < 4; tm++)
#pragma unroll
                for (int tn = 0; tn < TN; tn++)
                    mma_fp8(acc[tm][tn], af[cur][tm], bf[cur][tn]);
        }
        __syncthreads();

        // ---- per-M-tile epilogue ----
        if (kc == 3) {
            const int rowBase = (it >> 2) * 128;
            float rs[4][2];
#pragma unroll
            for (int tm = 0; tm < 4; tm++) { rs[tm][0] = 0.f; rs[tm][1] = 0.f; }
#pragma unroll
            for (int tn = 0; tn < TN; tn++) {
                int lc = warpN + tn * 8 + 2 * lm;
                int gc0 = colBase + lc, gc1 = gc0 + 1;
                float m0 = (gc0 < NCLS) ? 1.f : 0.f;
                float m1 = (gc1 < NCLS) ? 1.f : 0.f;
#pragma unroll
                for (int tm = 0; tm < 4; tm++) {
                    // logit = 64*cos = acc * 0.25 (acc = 256*cos); clamp [-64,64]
                    float c0 = fminf(fmaxf(acc[tm][tn][0] * 0.25f, -64.f), 64.f);
                    float c1 = fminf(fmaxf(acc[tm][tn][1] * 0.25f, -64.f), 64.f);
                    float c2 = fminf(fmaxf(acc[tm][tn][2] * 0.25f, -64.f), 64.f);
                    float c3 = fminf(fmaxf(acc[tm][tn][3] * 0.25f, -64.f), 64.f);
                    rs[tm][0] += m0 * __expf(c0 - 64.f) + m1 * __expf(c1 - 64.f);
                    rs[tm][1] += m0 * __expf(c2 - 64.f) + m1 * __expf(c3 - 64.f);
                    acc[tm][tn][0] = 0.f; acc[tm][tn][1] = 0.f;
                    acc[tm][tn][2] = 0.f; acc[tm][tn][3] = 0.f;
                }
            }
#pragma unroll
            for (int tm = 0; tm < 4; tm++)
#pragma unroll
                for (int h = 0; h < 2; h++) {
                    float v = rs[tm][h];
                    v += __shfl_xor_sync(0xffffffffu, v, 1);
                    v += __shfl_xor_sync(0xffffffffu, v, 2);
                    rs[tm][h] = v;
                }
            if (lm == 0) {
                int wn = wid >> 1;
#pragma unroll
                for (int tm = 0; tm < 4; tm++) {
                    int r0 = warpM + tm * 16 + l4;
                    s_red[wn * 128 + r0] = rs[tm][0];
                    s_red[wn * 128 + r0 + 8] = rs[tm][1];
                }
            }
            __syncthreads();
            if (tid < 128) {
                float s = s_red[tid] + s_red[128 + tid] + s_red[256 + tid] + s_red[384 + tid];
                atomicAdd(&g_sum[rowBase + tid], s);
            }
        }
    }
}

// Kernel 2: merged GEMM launch. First NB4 blocks: 128-col tiles; rest: 96-col.
__global__ void __launch_bounds__(256, 2)
k_main_fp8(const float* __restrict__ w) {
    if (blockIdx.x < NB4) {
        gemm_body<4>(w, blockIdx.x * 128);
    } else {
        gemm_body<3>(w, NB4 * 128 + (blockIdx.x - NB4) * 96);
    }
}

// ---------------------------------------------------------------------------
// Kernel 3: exact fp32 label cos -> margin target, PLUS fp8-replica label
// logit (same quantization as the GEMM prologue) for near-exact cancellation.
__global__ void k_label(const float* __restrict__ w, const int* __restrict__ labels) {
    int wp = threadIdx.x >> 5, lane = threadIdx.x & 31;
    int n = blockIdx.x * 8 + wp;
    if (n >= NROWS) return;
    int lab = labels[n];
    const float4* frf = (const float4*)(g_fn + n * DIM);
    const float4* wrf = (const float4*)(w + (size_t)lab * DIM);
    // Lane owns k in [lane*16, lane*16+16): float4 indices lane*4 + i.
    float4 wv[4], fv[4];
    float dot = 0.f, ss = 0.f;
#pragma unroll
    for (int i = 0; i < 4; i++) {
        wv[i] = wrf[lane * 4 + i];
        fv[i] = frf[lane * 4 + i];
        dot += fv[i].x * wv[i].x + fv[i].y * wv[i].y + fv[i].z * wv[i].z + fv[i].w * wv[i].w;
        ss += wv[i].x * wv[i].x + wv[i].y * wv[i].y + wv[i].z * wv[i].z + wv[i].w * wv[i].w;
    }
#pragma unroll
    for (int off = 16; off > 0; off >>= 1) {
        dot += __shfl_xor_sync(0xffffffffu, dot, off);
        ss += __shfl_xor_sync(0xffffffffu, ss, off);
    }
    float rinv = 1.f / fmaxf(sqrtf(ss), 1e-12f);
    float rs16 = rinv * FP8_SCALE;
    // fp8-replica dot: quantize W like the GEMM prologue; A from g_fnb8.
    float d8 = 0.f;
#pragma unroll
    for (int i = 0; i < 4; i++) {
        int k0 = lane * 16 + 4 * i;
        float ax, ay, az, aw;
        e4m3x2_to_ff(g_fnb8[a_pack_byte(n, k0) >> 1], ax, ay);
        e4m3x2_to_ff(g_fnb8[a_pack_byte(n, k0 + 2) >> 1], az, aw);
        float bx, by, bz, bw;
        e4m3x2_to_ff(cvt_e4m3x2(wv[i].y * rs16, wv[i].x * rs16), bx, by);
        e4m3x2_to_ff(cvt_e4m3x2(wv[i].w * rs16, wv[i].z * rs16), bz, bw);
        d8 += ax * bx + ay * by + az * bz + aw * bw;
    }
#pragma unroll
    for (int off = 16; off > 0; off >>= 1)
        d8 += __shfl_xor_sync(0xffffffffu, d8, off);
    if (lane == 0) {
        float cosv = fminf(fmaxf(dot * rinv, -1.f), 1.f);
        float sinv = sqrtf(1.f - cosv * cosv + 1e-5f);
        float cm = cosv * COS_M - sinv * SIN_M;
        g_tgt[n] = (cosv > MIN_COS) ? cm : (cosv - sinv * MARG);
        g_cosl[n] = fminf(fmaxf(d8 * 0.25f, -64.f), 64.f);   // replica label logit
    }
}

// ---------------------------------------------------------------------------
// Kernel 4: label swap, NLL, mean. g_sum already accumulated.
__global__ void k_final(float* __restrict__ out) {
    int t = threadIdx.x;
    float s = g_sum[t];
    float cl = g_cosl[t];                        // (replica of) label logit inside s
    float tgt = g_tgt[t];
    float s2 = s - expf(cl - 64.f) + expf(SCALE * tgt - 64.f);
    float nll = 64.f + logf(s2) - SCALE * tgt;

    __shared__ float sred[1024];
    sred[t] = nll;
    __syncthreads();
    for (int off = 512; off > 0; off >>= 1) {
        if (t < off) sred[t] += sred[t + off];
        __syncthreads();
    }
    if (t == 0) out[0] = sred[0] * (1.0f / (float)NROWS);
}

// ---------------------------------------------------------------------------
extern "C" void kernel_launch(void* const* d_in, const int* in_sizes, int n_in,
                              void* d_out, int out_size) {
    const float* feats = (const float*)d_in[0];
    const float* w = (const float*)d_in[1];
    const int* labels = (const int*)d_in[2];
    float* out = (float*)d_out;

    cudaFuncSetAttribute(k_main_fp8, cudaFuncAttributeMaxDynamicSharedMemorySize, SMEM_BYTES);

    k_norm_feats<<<NROWS, 128>>>(feats);
    k_main_fp8<<<NB4 + NB3, 256, SMEM_BYTES>>>(w);
    k_label<<<NROWS / 8, 256>>>(w, labels);
    k_final<<<1, 1024>>>(out);
}